// round 1
// baseline (speedup 1.0000x reference)
#include <cuda_runtime.h>

#define DIM_NODE 64
#define DIM_EDGE 32
#define D_IN1    160
#define D_H      128
#define OUT_DIM  64
#define MAX_NODES 50000
#define E_TILE   64
#define NEG_SLOPE 0.01f

// Per-node precomputed partial products: P[n][0:128]   = x[n] @ W1a^T
//                                        P[n][128:256] = x[n] @ W1b^T
__device__ float g_P[(size_t)MAX_NODES * 256];

// ---------------------------------------------------------------------------
// Kernel 1: node precompute.  32 nodes / block, 256 threads.
// smem: s_w[64][257] (transposed combined 256x64 weight), s_x[32][68]
// ---------------------------------------------------------------------------
__global__ __launch_bounds__(256) void k_precompute(
    const float* __restrict__ x, const float* __restrict__ W1, int n_nodes)
{
    extern __shared__ float sm[];
    float* s_w = sm;               // [64][257] : s_w[d*257 + c], c in 0..255
    float* s_x = sm + 64 * 257;    // [32][68]

    const int t = threadIdx.x;

    // Load combined weight W[c][d] (c<128 -> W1[c][d], c>=128 -> W1[c-128][64+d])
    // stored transposed as s_w[d][c].  Coalesced over d.
    #pragma unroll
    for (int i = 0; i < 64; ++i) {
        int idx = i * 256 + t;            // 0..16383
        int c = idx >> 6;                 // 0..255
        int d = idx & 63;
        float v = (c < 128) ? W1[c * D_IN1 + d]
                            : W1[(c - 128) * D_IN1 + 64 + d];
        s_w[d * 257 + c] = v;
    }

    const int node0 = blockIdx.x * 32;
    #pragma unroll
    for (int i = 0; i < 8; ++i) {
        int idx = i * 256 + t;            // 0..2047
        int n = idx >> 6;
        int d = idx & 63;
        int gn = node0 + n;
        s_x[n * 68 + d] = (gn < n_nodes) ? x[(size_t)gn * DIM_NODE + d] : 0.f;
    }
    __syncthreads();

    // Each thread: 4 nodes x 8 cols microtile
    const int n0 = t & 7;                 // node lane 0..7 (nodes n0 + 8i)
    const int c0 = (t >> 3) * 8;          // col group 0..248

    float acc[4][8];
    #pragma unroll
    for (int i = 0; i < 4; ++i)
        #pragma unroll
        for (int j = 0; j < 8; ++j) acc[i][j] = 0.f;

    #pragma unroll 4
    for (int d = 0; d < 64; ++d) {
        float xa[4], wb[8];
        #pragma unroll
        for (int i = 0; i < 4; ++i) xa[i] = s_x[(n0 + 8 * i) * 68 + d];
        #pragma unroll
        for (int j = 0; j < 8; ++j) wb[j] = s_w[d * 257 + c0 + j];
        #pragma unroll
        for (int i = 0; i < 4; ++i)
            #pragma unroll
            for (int j = 0; j < 8; ++j)
                acc[i][j] = fmaf(xa[i], wb[j], acc[i][j]);
    }

    #pragma unroll
    for (int i = 0; i < 4; ++i) {
        int gn = node0 + n0 + 8 * i;
        if (gn < n_nodes) {
            float4* p = (float4*)(g_P + (size_t)gn * 256 + c0);
            p[0] = make_float4(acc[i][0], acc[i][1], acc[i][2], acc[i][3]);
            p[1] = make_float4(acc[i][4], acc[i][5], acc[i][6], acc[i][7]);
        }
    }
}

// ---------------------------------------------------------------------------
// Kernel 2: fused edge MLP.  64 edges / block, 256 threads.
//   stage2: h[64][128] = ea@W1c^T + P_src + P_dst + b1, leaky  -> smem
//   stage3: out[64][64] = h @ W2^T + b2
// ---------------------------------------------------------------------------
__global__ __launch_bounds__(256) void k_edge(
    const int*   __restrict__ eidx,   // [2*E]: [0..E) src, [E..2E) dst
    const float* __restrict__ ea,     // [E][32]
    const float* __restrict__ W1,     // [128][160]
    const float* __restrict__ b1,     // [128]
    const float* __restrict__ W2,     // [64][128]
    const float* __restrict__ b2,     // [64]
    float*       __restrict__ out,    // [E][64]
    int E)
{
    extern __shared__ float sm[];
    float* s_ea  = sm;                    // [64][33]
    float* s_w1c = s_ea  + 64 * 33;       // [128][32]
    float* s_h   = s_w1c + 128 * 32;      // [64][132]
    float* s_w2  = s_h   + 64 * 132;      // [64][128]
    float* s_b1  = s_w2  + 64 * 128;      // [128]
    float* s_b2  = s_b1  + 128;           // [64]
    int*   s_src = (int*)(s_b2 + 64);     // [64]
    int*   s_dst = s_src + 64;            // [64]

    const int t = threadIdx.x;
    const int ebase = blockIdx.x * E_TILE;

    // --- stage 1: load weights / tile ---
    #pragma unroll
    for (int i = 0; i < 16; ++i) {        // 128*32 = 4096
        int idx = i * 256 + t;
        s_w1c[idx] = W1[(idx >> 5) * D_IN1 + 128 + (idx & 31)];
    }
    #pragma unroll
    for (int i = 0; i < 32; ++i) {        // 64*128 = 8192
        int idx = i * 256 + t;
        s_w2[idx] = W2[idx];
    }
    if (t < 128)      s_b1[t] = b1[t];
    else if (t < 192) s_b2[t - 128] = b2[t - 128];

    if (t < 64) {
        int e = ebase + t;
        s_src[t] = (e < E) ? eidx[e] : 0;
        s_dst[t] = (e < E) ? eidx[E + e] : 0;
    }
    #pragma unroll
    for (int i = 0; i < 8; ++i) {         // 64*32 = 2048
        int idx = i * 256 + t;
        int e = idx >> 5, d = idx & 31;
        int ge = ebase + e;
        s_ea[e * 33 + d] = (ge < E) ? ea[(size_t)ge * DIM_EDGE + d] : 0.f;
    }
    __syncthreads();

    const int e0 = t & 15;                // edge lane 0..15 (edges e0 + 16i)
    const int g8 = t >> 4;                // 0..15

    // --- stage 2: h = ea @ W1c^T + P gathers + b1, leaky ---
    {
        const int k0 = g8 * 8;            // 8 h-cols per thread
        float acc[4][8];
        #pragma unroll
        for (int i = 0; i < 4; ++i)
            #pragma unroll
            for (int j = 0; j < 8; ++j) acc[i][j] = s_b1[k0 + j];

        #pragma unroll 4
        for (int d = 0; d < 32; ++d) {
            float xa[4], wb[8];
            #pragma unroll
            for (int i = 0; i < 4; ++i) xa[i] = s_ea[(e0 + 16 * i) * 33 + d];
            #pragma unroll
            for (int j = 0; j < 8; ++j) wb[j] = s_w1c[(k0 + j) * 32 + d];
            #pragma unroll
            for (int i = 0; i < 4; ++i)
                #pragma unroll
                for (int j = 0; j < 8; ++j)
                    acc[i][j] = fmaf(xa[i], wb[j], acc[i][j]);
        }

        #pragma unroll
        for (int i = 0; i < 4; ++i) {
            int e = e0 + 16 * i;
            const float4* ps = (const float4*)(g_P + (size_t)s_src[e] * 256 + k0);
            const float4* pd = (const float4*)(g_P + (size_t)s_dst[e] * 256 + 128 + k0);
            float4 a0 = ps[0], a1 = ps[1];
            float4 q0 = pd[0], q1 = pd[1];
            float h[8];
            h[0] = acc[i][0] + a0.x + q0.x;
            h[1] = acc[i][1] + a0.y + q0.y;
            h[2] = acc[i][2] + a0.z + q0.z;
            h[3] = acc[i][3] + a0.w + q0.w;
            h[4] = acc[i][4] + a1.x + q1.x;
            h[5] = acc[i][5] + a1.y + q1.y;
            h[6] = acc[i][6] + a1.z + q1.z;
            h[7] = acc[i][7] + a1.w + q1.w;
            #pragma unroll
            for (int j = 0; j < 8; ++j)
                h[j] = (h[j] >= 0.f) ? h[j] : NEG_SLOPE * h[j];
            float4* hp = (float4*)(s_h + e * 132 + k0);
            hp[0] = make_float4(h[0], h[1], h[2], h[3]);
            hp[1] = make_float4(h[4], h[5], h[6], h[7]);
        }
    }
    __syncthreads();

    // --- stage 3: out = leaky(h) @ W2^T + b2 ---
    {
        const int j0 = g8 * 4;            // 4 out-cols per thread
        float oacc[4][4];
        #pragma unroll
        for (int i = 0; i < 4; ++i)
            #pragma unroll
            for (int j = 0; j < 4; ++j) oacc[i][j] = s_b2[j0 + j];

        #pragma unroll 2
        for (int kk = 0; kk < 128; kk += 4) {
            float4 ha[4], wb[4];
            #pragma unroll
            for (int i = 0; i < 4; ++i)
                ha[i] = *(const float4*)(s_h + (e0 + 16 * i) * 132 + kk);
            #pragma unroll
            for (int j = 0; j < 4; ++j)
                wb[j] = *(const float4*)(s_w2 + (j0 + j) * 128 + kk);
            #pragma unroll
            for (int i = 0; i < 4; ++i)
                #pragma unroll
                for (int j = 0; j < 4; ++j) {
                    oacc[i][j] = fmaf(ha[i].x, wb[j].x, oacc[i][j]);
                    oacc[i][j] = fmaf(ha[i].y, wb[j].y, oacc[i][j]);
                    oacc[i][j] = fmaf(ha[i].z, wb[j].z, oacc[i][j]);
                    oacc[i][j] = fmaf(ha[i].w, wb[j].w, oacc[i][j]);
                }
        }

        #pragma unroll
        for (int i = 0; i < 4; ++i) {
            int ge = ebase + e0 + 16 * i;
            if (ge < E)
                *(float4*)(out + (size_t)ge * OUT_DIM + j0) =
                    make_float4(oacc[i][0], oacc[i][1], oacc[i][2], oacc[i][3]);
        }
    }
}

// ---------------------------------------------------------------------------
extern "C" void kernel_launch(void* const* d_in, const int* in_sizes, int n_in,
                              void* d_out, int out_size)
{
    const float* x    = (const float*)d_in[0];
    const int*   eidx = (const int*)  d_in[1];
    const float* ea   = (const float*)d_in[2];
    const float* W1   = (const float*)d_in[3];
    const float* b1   = (const float*)d_in[4];
    const float* W2   = (const float*)d_in[5];
    const float* b2   = (const float*)d_in[6];
    float* out = (float*)d_out;

    int n_nodes = in_sizes[0] / DIM_NODE;
    if (n_nodes > MAX_NODES) n_nodes = MAX_NODES;
    int E = in_sizes[2] / DIM_EDGE;

    const int smem1 = (64 * 257 + 32 * 68) * 4;                       // 74496 B
    const int smem2 = (64*33 + 128*32 + 64*132 + 64*128 + 128 + 64) * 4
                      + 128 * 4;                                      // 92672 B

    cudaFuncSetAttribute(k_precompute, cudaFuncAttributeMaxDynamicSharedMemorySize, smem1);
    cudaFuncSetAttribute(k_edge,       cudaFuncAttributeMaxDynamicSharedMemorySize, smem2);

    k_precompute<<<(n_nodes + 31) / 32, 256, smem1>>>(x, W1, n_nodes);
    k_edge<<<(E + E_TILE - 1) / E_TILE, 256, smem2>>>(eidx, ea, W1, b1, W2, b2, out, E);
}

// round 3
// speedup vs baseline: 2.4112x; 2.4112x over previous
#include <cuda_runtime.h>
#include <cstdint>

#define DIM_NODE 64
#define DIM_EDGE 32
#define D_IN1    160
#define OUT_DIM  64
#define MAX_NODES 50000
#define E_TILE   128
#define NEG_SLOPE 0.01f

// Per-node precomputed partials: P[n][0:128] = x[n]@W1a^T, P[n][128:256] = x[n]@W1b^T
__device__ float g_P[(size_t)MAX_NODES * 256];

__device__ __forceinline__ float to_tf32(float x) {
    uint32_t u; asm("cvt.rna.tf32.f32 %0, %1;" : "=r"(u) : "f"(x));
    return __uint_as_float(u);
}
__device__ __forceinline__ void mma_tf32(float* d, const uint32_t* a, const uint32_t* b) {
    asm volatile(
        "mma.sync.aligned.m16n8k8.row.col.f32.tf32.tf32.f32 "
        "{%0,%1,%2,%3}, {%4,%5,%6,%7}, {%8,%9}, {%0,%1,%2,%3};"
        : "+f"(d[0]), "+f"(d[1]), "+f"(d[2]), "+f"(d[3])
        : "r"(a[0]), "r"(a[1]), "r"(a[2]), "r"(a[3]), "r"(b[0]), "r"(b[1]));
}

// ---------------------------------------------------------------------------
// SMEM layout (floats).  Region0 is overlaid across phases.
//   phase A/1: s_ea [128][36] @0      s_w1c [128][36] @4608
//   phase B/2: s_h  [128][132] @0
//   epilogue : s_out[128][68]  @0
//   s_w2 [64][132] @16896,  b1 @25344, b2 @25472, src @25536, dst @25664
// ---------------------------------------------------------------------------
#define EA_F    0
#define W1C_F   4608
#define H_F     0
#define OUT_F   0
#define W2_F    16896
#define B1_F    25344
#define B2_F    25472
#define SRC_F   25536
#define DST_F   25664
#define SMEM_EDGE_FLOATS 25792          // 103168 bytes

// ---------------------------------------------------------------------------
// Kernel 1: node precompute.  64 nodes/block, 256 threads, 8x8 microtile.
// ---------------------------------------------------------------------------
__global__ __launch_bounds__(256, 2) void k_precompute(
    const float* __restrict__ x, const float* __restrict__ W1, int n_nodes)
{
    extern __shared__ float sm[];
    float* s_w = sm;               // [64][257]
    float* s_x = sm + 64 * 257;    // [64][68]
    const int t = threadIdx.x;

    #pragma unroll
    for (int i = 0; i < 64; ++i) {
        int idx = i * 256 + t;
        int c = idx >> 6, d = idx & 63;
        float v = (c < 128) ? W1[c * D_IN1 + d] : W1[(c - 128) * D_IN1 + 64 + d];
        s_w[d * 257 + c] = v;
    }
    const int node0 = blockIdx.x * 64;
    #pragma unroll
    for (int i = 0; i < 16; ++i) {
        int idx = i * 256 + t;
        int n = idx >> 6, d = idx & 63;
        int gn = node0 + n;
        s_x[n * 68 + d] = (gn < n_nodes) ? x[(size_t)gn * DIM_NODE + d] : 0.f;
    }
    __syncthreads();

    const int n0 = t & 7;
    const int c0 = (t >> 3) * 8;
    float acc[8][8];
    #pragma unroll
    for (int i = 0; i < 8; ++i)
        #pragma unroll
        for (int j = 0; j < 8; ++j) acc[i][j] = 0.f;

    #pragma unroll 4
    for (int d = 0; d < 64; ++d) {
        float xa[8], wb[8];
        #pragma unroll
        for (int i = 0; i < 8; ++i) xa[i] = s_x[(n0 + 8 * i) * 68 + d];
        #pragma unroll
        for (int j = 0; j < 8; ++j) wb[j] = s_w[d * 257 + c0 + j];
        #pragma unroll
        for (int i = 0; i < 8; ++i)
            #pragma unroll
            for (int j = 0; j < 8; ++j)
                acc[i][j] = fmaf(xa[i], wb[j], acc[i][j]);
    }
    #pragma unroll
    for (int i = 0; i < 8; ++i) {
        int gn = node0 + n0 + 8 * i;
        if (gn < n_nodes) {
            float4* p = (float4*)(g_P + (size_t)gn * 256 + c0);
            p[0] = make_float4(acc[i][0], acc[i][1], acc[i][2], acc[i][3]);
            p[1] = make_float4(acc[i][4], acc[i][5], acc[i][6], acc[i][7]);
        }
    }
}

// ---------------------------------------------------------------------------
// Kernel 2: mma.sync tf32 edge MLP.  128 edges/CTA, 256 threads (8 warps).
// ---------------------------------------------------------------------------
__global__ __launch_bounds__(256, 2) void k_edge(
    const int*   __restrict__ eidx,
    const float* __restrict__ ea,
    const float* __restrict__ W1,
    const float* __restrict__ b1,
    const float* __restrict__ W2g,
    const float* __restrict__ b2,
    float*       __restrict__ out,
    int E)
{
    extern __shared__ float sm[];
    const int t   = threadIdx.x;
    const int wid = t >> 5;
    const int lid = t & 31;
    const int qr  = lid >> 2;      // 0..7
    const int ql  = lid & 3;       // 0..3
    const int wm  = wid & 3;       // warp M coord (rows of 32)
    const int wn  = wid >> 2;      // warp N coord
    const int ebase = blockIdx.x * E_TILE;

    int* s_src = (int*)(sm + SRC_F);
    int* s_dst = (int*)(sm + DST_F);

    // ======== Phase A: stage operands ========
    // ea: [128 m][36] tf32
    #pragma unroll
    for (int i = 0; i < 4; ++i) {
        int idx = i * 256 + t;                // float4 id, 0..1023
        int m = idx >> 3, kc = idx & 7;
        int ge = ebase + m;
        float4 v = make_float4(0.f, 0.f, 0.f, 0.f);
        if (ge < E) v = ((const float4*)ea)[(size_t)ge * 8 + kc];
        v.x = to_tf32(v.x); v.y = to_tf32(v.y); v.z = to_tf32(v.z); v.w = to_tf32(v.w);
        *(float4*)(sm + EA_F + m * 36 + kc * 4) = v;
    }
    // W1c: [128 n][36] tf32 (cols 128..159 of W1)
    #pragma unroll
    for (int i = 0; i < 4; ++i) {
        int idx = i * 256 + t;
        int n = idx >> 3, kc = idx & 7;
        float4 v = *(const float4*)(W1 + n * D_IN1 + 128 + kc * 4);
        v.x = to_tf32(v.x); v.y = to_tf32(v.y); v.z = to_tf32(v.z); v.w = to_tf32(v.w);
        *(float4*)(sm + W1C_F + n * 36 + kc * 4) = v;
    }
    // W2: [64 n][132] tf32
    #pragma unroll
    for (int i = 0; i < 8; ++i) {
        int idx = i * 256 + t;                // 0..2047
        int n = idx >> 5, kc = idx & 31;
        float4 v = ((const float4*)W2g)[n * 32 + kc];
        v.x = to_tf32(v.x); v.y = to_tf32(v.y); v.z = to_tf32(v.z); v.w = to_tf32(v.w);
        *(float4*)(sm + W2_F + n * 132 + kc * 4) = v;
    }
    if (t < 128) {
        sm[B1_F + t] = b1[t];
        int e = ebase + t;
        s_src[t] = (e < E) ? eidx[e] : 0;
    } else {
        if (t < 192) sm[B2_F + t - 128] = b2[t - 128];
        int e = ebase + (t - 128);
        s_dst[t - 128] = (e < E) ? eidx[E + e] : 0;
    }
    __syncthreads();

    // ======== GEMM1: C1[128x128] = ea @ W1c^T  (M=32,N=64 per warp) ========
    float acc1[2][8][4];
    #pragma unroll
    for (int i = 0; i < 2; ++i)
        #pragma unroll
        for (int j = 0; j < 8; ++j)
            #pragma unroll
            for (int c = 0; c < 4; ++c) acc1[i][j][c] = 0.f;
    {
        const uint32_t* u_ea  = (const uint32_t*)(sm + EA_F);
        const uint32_t* u_w1c = (const uint32_t*)(sm + W1C_F);
        #pragma unroll
        for (int kt = 0; kt < 4; ++kt) {
            const int k = kt * 8 + ql;
            uint32_t a[2][4];
            #pragma unroll
            for (int i = 0; i < 2; ++i) {
                int r = wm * 32 + i * 16 + qr;
                a[i][0] = u_ea[r * 36 + k];
                a[i][1] = u_ea[(r + 8) * 36 + k];
                a[i][2] = u_ea[r * 36 + k + 4];
                a[i][3] = u_ea[(r + 8) * 36 + k + 4];
            }
            uint32_t b[8][2];
            #pragma unroll
            for (int j = 0; j < 8; ++j) {
                int n = wn * 64 + j * 8 + qr;
                b[j][0] = u_w1c[n * 36 + k];
                b[j][1] = u_w1c[n * 36 + k + 4];
            }
            #pragma unroll
            for (int i = 0; i < 2; ++i)
                #pragma unroll
                for (int j = 0; j < 8; ++j)
                    mma_tf32(acc1[i][j], a[i], b[j]);
        }
    }
    __syncthreads();   // everyone done reading ea/w1c; region0 becomes s_h

    // STS C1 -> s_h [128 m][132]
    #pragma unroll
    for (int i = 0; i < 2; ++i) {
        int r = wm * 32 + i * 16 + qr;
        #pragma unroll
        for (int j = 0; j < 8; ++j) {
            int c = wn * 64 + j * 8 + 2 * ql;
            *(float2*)(sm + H_F + r * 132 + c)       = make_float2(acc1[i][j][0], acc1[i][j][1]);
            *(float2*)(sm + H_F + (r + 8) * 132 + c) = make_float2(acc1[i][j][2], acc1[i][j][3]);
        }
    }
    __syncthreads();

    // ======== Phase B: h = tf32(leaky(C1 + P_src + P_dst + b1)) in place ======
    {
        const int m0 = wid * 16;
        const float4 bb1 = *(const float4*)(sm + B1_F + 4 * lid);
        #pragma unroll
        for (int g = 0; g < 16; g += 4) {
            float4 vs[4], vd[4], hh[4];
            #pragma unroll
            for (int r = 0; r < 4; ++r) {
                int m = m0 + g + r;
                vs[r] = *(const float4*)(g_P + (size_t)s_src[m] * 256 + 4 * lid);
                vd[r] = *(const float4*)(g_P + (size_t)s_dst[m] * 256 + 128 + 4 * lid);
            }
            #pragma unroll
            for (int r = 0; r < 4; ++r)
                hh[r] = *(const float4*)(sm + H_F + (m0 + g + r) * 132 + 4 * lid);
            #pragma unroll
            for (int r = 0; r < 4; ++r) {
                float h0 = hh[r].x + vs[r].x + vd[r].x + bb1.x;
                float h1 = hh[r].y + vs[r].y + vd[r].y + bb1.y;
                float h2 = hh[r].z + vs[r].z + vd[r].z + bb1.z;
                float h3 = hh[r].w + vs[r].w + vd[r].w + bb1.w;
                h0 = (h0 >= 0.f) ? h0 : NEG_SLOPE * h0;
                h1 = (h1 >= 0.f) ? h1 : NEG_SLOPE * h1;
                h2 = (h2 >= 0.f) ? h2 : NEG_SLOPE * h2;
                h3 = (h3 >= 0.f) ? h3 : NEG_SLOPE * h3;
                *(float4*)(sm + H_F + (m0 + g + r) * 132 + 4 * lid) =
                    make_float4(to_tf32(h0), to_tf32(h1), to_tf32(h2), to_tf32(h3));
            }
        }
    }
    __syncthreads();

    // ======== GEMM2: C2[128x64] = h @ W2^T  (M=32,N=32 per warp) ========
    float acc2[2][4][4];
    #pragma unroll
    for (int i = 0; i < 2; ++i)
        #pragma unroll
        for (int j = 0; j < 4; ++j)
            #pragma unroll
            for (int c = 0; c < 4; ++c) acc2[i][j][c] = 0.f;
    {
        const uint32_t* u_h  = (const uint32_t*)(sm + H_F);
        const uint32_t* u_w2 = (const uint32_t*)(sm + W2_F);
        #pragma unroll
        for (int kt = 0; kt < 16; ++kt) {
            const int k = kt * 8 + ql;
            uint32_t a[2][4];
            #pragma unroll
            for (int i = 0; i < 2; ++i) {
                int r = wm * 32 + i * 16 + qr;
                a[i][0] = u_h[r * 132 + k];
                a[i][1] = u_h[(r + 8) * 132 + k];
                a[i][2] = u_h[r * 132 + k + 4];
                a[i][3] = u_h[(r + 8) * 132 + k + 4];
            }
            uint32_t b[4][2];
            #pragma unroll
            for (int j = 0; j < 4; ++j) {
                int n = wn * 32 + j * 8 + qr;
                b[j][0] = u_w2[n * 132 + k];
                b[j][1] = u_w2[n * 132 + k + 4];
            }
            #pragma unroll
            for (int i = 0; i < 2; ++i)
                #pragma unroll
                for (int j = 0; j < 4; ++j)
                    mma_tf32(acc2[i][j], a[i], b[j]);
        }
    }
    __syncthreads();   // done reading s_h; region0 becomes s_out

    // STS C2 -> s_out [128 m][68]
    #pragma unroll
    for (int i = 0; i < 2; ++i) {
        int r = wm * 32 + i * 16 + qr;
        #pragma unroll
        for (int j = 0; j < 4; ++j) {
            int c = wn * 32 + j * 8 + 2 * ql;
            *(float2*)(sm + OUT_F + r * 68 + c)       = make_float2(acc2[i][j][0], acc2[i][j][1]);
            *(float2*)(sm + OUT_F + (r + 8) * 68 + c) = make_float2(acc2[i][j][2], acc2[i][j][3]);
        }
    }
    __syncthreads();

    // ======== Final: out = s_out + b2, coalesced row stores ========
    {
        const int m0 = wid * 16;
        const float2 bb2 = *(const float2*)(sm + B2_F + 2 * lid);
        #pragma unroll
        for (int r = 0; r < 16; ++r) {
            int m = m0 + r;
            int ge = ebase + m;
            if (ge < E) {
                float2 v = *(const float2*)(sm + OUT_F + m * 68 + 2 * lid);
                v.x += bb2.x; v.y += bb2.y;
                *(float2*)(out + (size_t)ge * OUT_DIM + 2 * lid) = v;
            }
        }
    }
}

// ---------------------------------------------------------------------------
extern "C" void kernel_launch(void* const* d_in, const int* in_sizes, int n_in,
                              void* d_out, int out_size)
{
    const float* x    = (const float*)d_in[0];
    const int*   eidx = (const int*)  d_in[1];
    const float* ea   = (const float*)d_in[2];
    const float* W1   = (const float*)d_in[3];
    const float* b1   = (const float*)d_in[4];
    const float* W2   = (const float*)d_in[5];
    const float* b2   = (const float*)d_in[6];
    float* out = (float*)d_out;

    int n_nodes = in_sizes[0] / DIM_NODE;
    if (n_nodes > MAX_NODES) n_nodes = MAX_NODES;
    int E = in_sizes[2] / DIM_EDGE;

    const int smem1 = (64 * 257 + 64 * 68) * 4;       // 83200 B
    const int smem2 = SMEM_EDGE_FLOATS * 4;           // 103168 B

    cudaFuncSetAttribute(k_precompute, cudaFuncAttributeMaxDynamicSharedMemorySize, smem1);
    cudaFuncSetAttribute(k_edge,       cudaFuncAttributeMaxDynamicSharedMemorySize, smem2);

    k_precompute<<<(n_nodes + 63) / 64, 256, smem1>>>(x, W1, n_nodes);
    k_edge<<<(E + E_TILE - 1) / E_TILE, 256, smem2>>>(eidx, ea, W1, b1, W2, b2, out, E);
}

// round 4
// speedup vs baseline: 2.5327x; 1.0504x over previous
#include <cuda_runtime.h>
#include <cstdint>

#define DIM_NODE 64
#define DIM_EDGE 32
#define D_IN1    160
#define OUT_DIM  64
#define MAX_NODES 50000
#define E_TILE   128
#define NEG_SLOPE 0.01f

// Per-node precomputed partials: P[n][0:128] = x[n]@W1a^T, P[n][128:256] = x[n]@W1b^T
__device__ float g_P[(size_t)MAX_NODES * 256];

__device__ __forceinline__ float to_tf32(float x) {
    uint32_t u; asm("cvt.rna.tf32.f32 %0, %1;" : "=r"(u) : "f"(x));
    return __uint_as_float(u);
}
__device__ __forceinline__ void mma_tf32(float* d, const uint32_t* a, const uint32_t* b) {
    asm volatile(
        "mma.sync.aligned.m16n8k8.row.col.f32.tf32.tf32.f32 "
        "{%0,%1,%2,%3}, {%4,%5,%6,%7}, {%8,%9}, {%0,%1,%2,%3};"
        : "+f"(d[0]), "+f"(d[1]), "+f"(d[2]), "+f"(d[3])
        : "r"(a[0]), "r"(a[1]), "r"(a[2]), "r"(a[3]), "r"(b[0]), "r"(b[1]));
}

// ---------------------------------------------------------------------------
// SMEM layout (floats).  Region0 [128][132] is overlaid across phases:
//   staging/GEMM1: s_ea [128][36] @0, s_w1c [128][36] @4608
//   after GEMM1  : s_h  [128][132] @0   (C1, then h in place)
// Persistent: s_w2 [64][132] @16896, b1 @25344, b2 @25472, src/dst @25536/25664
// ---------------------------------------------------------------------------
#define EA_F    0
#define W1C_F   4608
#define H_F     0
#define W2_F    16896
#define B1_F    25344
#define B2_F    25472
#define SRC_F   25536
#define DST_F   25664
#define SMEM_EDGE_FLOATS 25792          // 103168 bytes

// ---------------------------------------------------------------------------
// Kernel 1: node precompute.  64 nodes/block, 256 threads, 8x8 microtile.
// ---------------------------------------------------------------------------
__global__ __launch_bounds__(256, 2) void k_precompute(
    const float* __restrict__ x, const float* __restrict__ W1, int n_nodes)
{
    extern __shared__ float sm[];
    float* s_w = sm;               // [64][257]
    float* s_x = sm + 64 * 257;    // [64][68]
    const int t = threadIdx.x;

    #pragma unroll
    for (int i = 0; i < 64; ++i) {
        int idx = i * 256 + t;
        int c = idx >> 6, d = idx & 63;
        float v = (c < 128) ? W1[c * D_IN1 + d] : W1[(c - 128) * D_IN1 + 64 + d];
        s_w[d * 257 + c] = v;
    }
    const int node0 = blockIdx.x * 64;
    #pragma unroll
    for (int i = 0; i < 16; ++i) {
        int idx = i * 256 + t;
        int n = idx >> 6, d = idx & 63;
        int gn = node0 + n;
        s_x[n * 68 + d] = (gn < n_nodes) ? x[(size_t)gn * DIM_NODE + d] : 0.f;
    }
    __syncthreads();

    const int n0 = t & 7;
    const int c0 = (t >> 3) * 8;
    float acc[8][8];
    #pragma unroll
    for (int i = 0; i < 8; ++i)
        #pragma unroll
        for (int j = 0; j < 8; ++j) acc[i][j] = 0.f;

    #pragma unroll 4
    for (int d = 0; d < 64; ++d) {
        float xa[8], wb[8];
        #pragma unroll
        for (int i = 0; i < 8; ++i) xa[i] = s_x[(n0 + 8 * i) * 68 + d];
        #pragma unroll
        for (int j = 0; j < 8; ++j) wb[j] = s_w[d * 257 + c0 + j];
        #pragma unroll
        for (int i = 0; i < 8; ++i)
            #pragma unroll
            for (int j = 0; j < 8; ++j)
                acc[i][j] = fmaf(xa[i], wb[j], acc[i][j]);
    }
    #pragma unroll
    for (int i = 0; i < 8; ++i) {
        int gn = node0 + n0 + 8 * i;
        if (gn < n_nodes) {
            float4* p = (float4*)(g_P + (size_t)gn * 256 + c0);
            p[0] = make_float4(acc[i][0], acc[i][1], acc[i][2], acc[i][3]);
            p[1] = make_float4(acc[i][4], acc[i][5], acc[i][6], acc[i][7]);
        }
    }
}

// ---------------------------------------------------------------------------
// Kernel 2: persistent mma.sync tf32 edge MLP. 128 edges/tile, 8 warps/CTA.
// ---------------------------------------------------------------------------
__global__ __launch_bounds__(256, 2) void k_edge(
    const int*   __restrict__ eidx,
    const float* __restrict__ ea,
    const float* __restrict__ W1,
    const float* __restrict__ b1,
    const float* __restrict__ W2g,
    const float* __restrict__ b2,
    float*       __restrict__ out,
    int E, int n_tiles)
{
    extern __shared__ float sm[];
    const int t   = threadIdx.x;
    const int wid = t >> 5;
    const int lid = t & 31;
    const int qr  = lid >> 2;      // 0..7
    const int ql  = lid & 3;       // 0..3
    const int wm  = wid & 3;       // warp M coord (rows of 32)
    const int wn  = wid >> 2;      // warp N coord

    int* s_src = (int*)(sm + SRC_F);
    int* s_dst = (int*)(sm + DST_F);

    // ======== CTA prologue: persistent weights (once) ========
    // W2: [64 n][132] tf32
    #pragma unroll
    for (int i = 0; i < 8; ++i) {
        int idx = i * 256 + t;                // 0..2047 float4s
        int n = idx >> 5, kc = idx & 31;
        float4 v = ((const float4*)W2g)[n * 32 + kc];
        v.x = to_tf32(v.x); v.y = to_tf32(v.y); v.z = to_tf32(v.z); v.w = to_tf32(v.w);
        *(float4*)(sm + W2_F + n * 132 + kc * 4) = v;
    }
    if (t < 128)      sm[B1_F + t] = b1[t];
    else if (t < 192) sm[B2_F + t - 128] = b2[t - 128];
    __syncthreads();

    // b2 fragment registers for the direct-STG epilogue
    float2 bb2[4];
    #pragma unroll
    for (int j = 0; j < 4; ++j)
        bb2[j] = *(const float2*)(sm + B2_F + wn * 32 + j * 8 + 2 * ql);
    const float4 bb1 = *(const float4*)(sm + B1_F + 4 * lid);

    // ======== persistent tile loop ========
    for (int tile = blockIdx.x; tile < n_tiles; tile += gridDim.x) {
        const int ebase = tile * E_TILE;

        // ---- stage ea / w1c / indices ----
        #pragma unroll
        for (int i = 0; i < 4; ++i) {
            int idx = i * 256 + t;            // float4 id, 0..1023
            int m = idx >> 3, kc = idx & 7;
            int ge = ebase + m;
            float4 v = make_float4(0.f, 0.f, 0.f, 0.f);
            if (ge < E) v = ((const float4*)ea)[(size_t)ge * 8 + kc];
            v.x = to_tf32(v.x); v.y = to_tf32(v.y); v.z = to_tf32(v.z); v.w = to_tf32(v.w);
            *(float4*)(sm + EA_F + m * 36 + kc * 4) = v;
        }
        #pragma unroll
        for (int i = 0; i < 4; ++i) {
            int idx = i * 256 + t;
            int n = idx >> 3, kc = idx & 7;
            float4 v = *(const float4*)(W1 + n * D_IN1 + 128 + kc * 4);
            v.x = to_tf32(v.x); v.y = to_tf32(v.y); v.z = to_tf32(v.z); v.w = to_tf32(v.w);
            *(float4*)(sm + W1C_F + n * 36 + kc * 4) = v;
        }
        if (t < 128) {
            int e = ebase + t;
            s_src[t] = (e < E) ? eidx[e] : 0;
        } else {
            int e = ebase + (t - 128);
            s_dst[t - 128] = (e < E) ? eidx[E + e] : 0;
        }
        __syncthreads();

        // ---- GEMM1: C1[128x128] = ea @ W1c^T  (M=32,N=64 per warp) ----
        float acc1[2][8][4];
        #pragma unroll
        for (int i = 0; i < 2; ++i)
            #pragma unroll
            for (int j = 0; j < 8; ++j)
                #pragma unroll
                for (int c = 0; c < 4; ++c) acc1[i][j][c] = 0.f;
        {
            const uint32_t* u_ea  = (const uint32_t*)(sm + EA_F);
            const uint32_t* u_w1c = (const uint32_t*)(sm + W1C_F);
            #pragma unroll
            for (int kt = 0; kt < 4; ++kt) {
                const int k = kt * 8 + ql;
                uint32_t a[2][4];
                #pragma unroll
                for (int i = 0; i < 2; ++i) {
                    int r = wm * 32 + i * 16 + qr;
                    a[i][0] = u_ea[r * 36 + k];
                    a[i][1] = u_ea[(r + 8) * 36 + k];
                    a[i][2] = u_ea[r * 36 + k + 4];
                    a[i][3] = u_ea[(r + 8) * 36 + k + 4];
                }
                uint32_t b[8][2];
                #pragma unroll
                for (int j = 0; j < 8; ++j) {
                    int n = wn * 64 + j * 8 + qr;
                    b[j][0] = u_w1c[n * 36 + k];
                    b[j][1] = u_w1c[n * 36 + k + 4];
                }
                #pragma unroll
                for (int i = 0; i < 2; ++i)
                    #pragma unroll
                    for (int j = 0; j < 8; ++j)
                        mma_tf32(acc1[i][j], a[i], b[j]);
            }
        }
        __syncthreads();   // done reading ea/w1c; region0 becomes C1/h

        // ---- STS C1 -> s_h [128 m][132] ----
        #pragma unroll
        for (int i = 0; i < 2; ++i) {
            int r = wm * 32 + i * 16 + qr;
            #pragma unroll
            for (int j = 0; j < 8; ++j) {
                int c = wn * 64 + j * 8 + 2 * ql;
                *(float2*)(sm + H_F + r * 132 + c)       = make_float2(acc1[i][j][0], acc1[i][j][1]);
                *(float2*)(sm + H_F + (r + 8) * 132 + c) = make_float2(acc1[i][j][2], acc1[i][j][3]);
            }
        }
        __syncthreads();

        // ---- Phase B: h = tf32(leaky(C1 + P_src + P_dst + b1)) in place ----
        {
            const int m0 = wid * 16;
            #pragma unroll
            for (int g = 0; g < 16; g += 4) {
                float4 vs[4], vd[4], hh[4];
                #pragma unroll
                for (int r = 0; r < 4; ++r) {
                    int m = m0 + g + r;
                    vs[r] = *(const float4*)(g_P + (size_t)s_src[m] * 256 + 4 * lid);
                    vd[r] = *(const float4*)(g_P + (size_t)s_dst[m] * 256 + 128 + 4 * lid);
                }
                #pragma unroll
                for (int r = 0; r < 4; ++r)
                    hh[r] = *(const float4*)(sm + H_F + (m0 + g + r) * 132 + 4 * lid);
                #pragma unroll
                for (int r = 0; r < 4; ++r) {
                    float h0 = hh[r].x + vs[r].x + vd[r].x + bb1.x;
                    float h1 = hh[r].y + vs[r].y + vd[r].y + bb1.y;
                    float h2 = hh[r].z + vs[r].z + vd[r].z + bb1.z;
                    float h3 = hh[r].w + vs[r].w + vd[r].w + bb1.w;
                    h0 = (h0 >= 0.f) ? h0 : NEG_SLOPE * h0;
                    h1 = (h1 >= 0.f) ? h1 : NEG_SLOPE * h1;
                    h2 = (h2 >= 0.f) ? h2 : NEG_SLOPE * h2;
                    h3 = (h3 >= 0.f) ? h3 : NEG_SLOPE * h3;
                    *(float4*)(sm + H_F + (m0 + g + r) * 132 + 4 * lid) =
                        make_float4(to_tf32(h0), to_tf32(h1), to_tf32(h2), to_tf32(h3));
                }
            }
        }
        __syncthreads();

        // ---- GEMM2: C2[128x64] = h @ W2^T  (M=32,N=32 per warp) ----
        float acc2[2][4][4];
        #pragma unroll
        for (int i = 0; i < 2; ++i)
            #pragma unroll
            for (int j = 0; j < 4; ++j)
                #pragma unroll
                for (int c = 0; c < 4; ++c) acc2[i][j][c] = 0.f;
        {
            const uint32_t* u_h  = (const uint32_t*)(sm + H_F);
            const uint32_t* u_w2 = (const uint32_t*)(sm + W2_F);
            #pragma unroll
            for (int kt = 0; kt < 16; ++kt) {
                const int k = kt * 8 + ql;
                uint32_t a[2][4];
                #pragma unroll
                for (int i = 0; i < 2; ++i) {
                    int r = wm * 32 + i * 16 + qr;
                    a[i][0] = u_h[r * 132 + k];
                    a[i][1] = u_h[(r + 8) * 132 + k];
                    a[i][2] = u_h[r * 132 + k + 4];
                    a[i][3] = u_h[(r + 8) * 132 + k + 4];
                }
                uint32_t b[4][2];
                #pragma unroll
                for (int j = 0; j < 4; ++j) {
                    int n = wn * 32 + j * 8 + qr;
                    b[j][0] = u_w2[n * 132 + k];
                    b[j][1] = u_w2[n * 132 + k + 4];
                }
                #pragma unroll
                for (int i = 0; i < 2; ++i)
                    #pragma unroll
                    for (int j = 0; j < 4; ++j)
                        mma_tf32(acc2[i][j], a[i], b[j]);
            }
        }

        // ---- Epilogue: direct STG from C2 fragments (+b2) ----
        #pragma unroll
        for (int i = 0; i < 2; ++i) {
            int r = wm * 32 + i * 16 + qr;
            int ge0 = ebase + r;
            int ge1 = ge0 + 8;
            #pragma unroll
            for (int j = 0; j < 4; ++j) {
                int c = wn * 32 + j * 8 + 2 * ql;
                if (ge0 < E)
                    *(float2*)(out + (size_t)ge0 * OUT_DIM + c) =
                        make_float2(acc2[i][j][0] + bb2[j].x, acc2[i][j][1] + bb2[j].y);
                if (ge1 < E)
                    *(float2*)(out + (size_t)ge1 * OUT_DIM + c) =
                        make_float2(acc2[i][j][2] + bb2[j].x, acc2[i][j][3] + bb2[j].y);
            }
        }
        __syncthreads();   // region0 free for next tile's staging
    }
}

// ---------------------------------------------------------------------------
extern "C" void kernel_launch(void* const* d_in, const int* in_sizes, int n_in,
                              void* d_out, int out_size)
{
    const float* x    = (const float*)d_in[0];
    const int*   eidx = (const int*)  d_in[1];
    const float* ea   = (const float*)d_in[2];
    const float* W1   = (const float*)d_in[3];
    const float* b1   = (const float*)d_in[4];
    const float* W2   = (const float*)d_in[5];
    const float* b2   = (const float*)d_in[6];
    float* out = (float*)d_out;

    int n_nodes = in_sizes[0] / DIM_NODE;
    if (n_nodes > MAX_NODES) n_nodes = MAX_NODES;
    int E = in_sizes[2] / DIM_EDGE;
    int n_tiles = (E + E_TILE - 1) / E_TILE;

    const int smem1 = (64 * 257 + 64 * 68) * 4;       // 83200 B
    const int smem2 = SMEM_EDGE_FLOATS * 4;           // 103168 B

    cudaFuncSetAttribute(k_precompute, cudaFuncAttributeMaxDynamicSharedMemorySize, smem1);
    cudaFuncSetAttribute(k_edge,       cudaFuncAttributeMaxDynamicSharedMemorySize, smem2);

    int n_blocks = 148 * 8;                            // 2 CTAs/SM * 4 waves
    if (n_blocks > n_tiles) n_blocks = n_tiles;

    k_precompute<<<(n_nodes + 63) / 64, 256, smem1>>>(x, W1, n_nodes);
    k_edge<<<n_blocks, 256, smem2>>>(eidx, ea, W1, b1, W2, b2, out, E, n_tiles);
}